// round 16
// baseline (speedup 1.0000x reference)
#include <cuda_runtime.h>
#include <cstdint>

// Problem constants (fixed by the reference setup)
#define B_   4
#define Q_   1024
#define D_   256
#define Hh   128
#define Ww   128
#define HW_  (Hh * Ww)
#define NH   8
#define NP   4
#define BQ   (B_ * Q_)          // 4096
#define SPLITS 4                 // split-K for final GEMM
#define KLEN2  ((NH * D_) / SPLITS)      // 2048/4 = 512

// ---------------- scratch (device globals; no allocations) ----------------
// Referenced ONLY from device code (by symbol) — kernel_launch performs no
// runtime API calls at all, so graph capture bakes nothing host-computed.
__device__ float g_img[(size_t)B_ * HW_ * D_];        // 64 MB: value @ W_v + b_v
__device__ float g_weighted[(size_t)BQ * NH * D_];    // 32 MB: [bq][h][d]
__device__ float g_part[(size_t)SPLITS * BQ * D_];    // 16 MB: split-K partials
__device__ float g_locs[(size_t)BQ * NH * NP * 2];    // 2 MB
__device__ float g_attn[(size_t)BQ * NH * NP];        // 0.5 MB

// =====================================================================
// SGEMM body: C[z][M,N] = A[:, k0:k0+kLen] * B[k0:k0+kLen, :] (+bias)
// Tile 128x128, TK=8, 256 threads, 8x8 microtile. Called from thin
// __global__ wrappers that bind scratch symbols directly.
// =====================================================================
#define TM 128
#define TN 128
#define TK 8

__device__ __forceinline__
void sgemm_body(const float* __restrict__ A, const float* __restrict__ Bm,
                const float* __restrict__ bias, float* __restrict__ C,
                int M, int N, int K, int kLen)
{
    __shared__ float As[TK][TM];
    __shared__ float Bs[TK][TN];

    const int tid = threadIdx.x;
    const int tm  = tid >> 4;          // 0..15 -> rows tm*8..tm*8+7
    const int tn  = tid & 15;          // 0..15 -> cols tn*8..tn*8+7
    const int row0 = blockIdx.x * TM;
    const int col0 = blockIdx.y * TN;
    const int k0   = blockIdx.z * kLen;

    float acc[8][8];
#pragma unroll
    for (int i = 0; i < 8; i++)
#pragma unroll
        for (int j = 0; j < 8; j++) acc[i][j] = 0.f;

    // A tile loader: thread -> (row = tid/2, kk = (tid&1)*4), one float4
    const int arow = tid >> 1;
    const int akk  = (tid & 1) * 4;
    // B tile loader: thread -> (k = tid/32, col = (tid&31)*4), one float4
    const int bk   = tid >> 5;
    const int bcol = (tid & 31) * 4;

    const float* Aptr = A + (size_t)(row0 + arow) * K + k0 + akk;
    const float* Bptr = Bm + (size_t)(k0 + bk) * N + col0 + bcol;

    for (int kt = 0; kt < kLen; kt += TK) {
        float4 a4 = *(const float4*)Aptr;
        float4 b4 = *(const float4*)Bptr;
        __syncthreads();                 // previous compute done before smem overwrite
        As[akk + 0][arow] = a4.x;
        As[akk + 1][arow] = a4.y;
        As[akk + 2][arow] = a4.z;
        As[akk + 3][arow] = a4.w;
        *(float4*)&Bs[bk][bcol] = b4;
        __syncthreads();                 // tiles visible before compute

#pragma unroll
        for (int kk = 0; kk < TK; kk++) {
            float4 a0 = *(const float4*)&As[kk][tm * 8];
            float4 a1 = *(const float4*)&As[kk][tm * 8 + 4];
            float4 b0 = *(const float4*)&Bs[kk][tn * 8];
            float4 b1 = *(const float4*)&Bs[kk][tn * 8 + 4];
            float ar[8] = {a0.x, a0.y, a0.z, a0.w, a1.x, a1.y, a1.z, a1.w};
            float br[8] = {b0.x, b0.y, b0.z, b0.w, b1.x, b1.y, b1.z, b1.w};
#pragma unroll
            for (int i = 0; i < 8; i++)
#pragma unroll
                for (int j = 0; j < 8; j++)
                    acc[i][j] = fmaf(ar[i], br[j], acc[i][j]);
        }
        Aptr += TK;
        Bptr += (size_t)TK * N;
    }

    float bv[8];
#pragma unroll
    for (int j = 0; j < 8; j++) bv[j] = bias ? bias[col0 + tn * 8 + j] : 0.f;

    float* Cbase = C + ((size_t)blockIdx.z * M + row0 + tm * 8) * N + col0 + tn * 8;
#pragma unroll
    for (int i = 0; i < 8; i++) {
        float4 o0 = {acc[i][0] + bv[0], acc[i][1] + bv[1],
                     acc[i][2] + bv[2], acc[i][3] + bv[3]};
        float4 o1 = {acc[i][4] + bv[4], acc[i][5] + bv[5],
                     acc[i][6] + bv[6], acc[i][7] + bv[7]};
        *(float4*)(Cbase + (size_t)i * N)     = o0;
        *(float4*)(Cbase + (size_t)i * N + 4) = o1;
    }
}

// GEMM1: g_img = value @ W_v + b_v     [65536,256] x [256,256]
__global__ __launch_bounds__(256, 2)
void gemm_img_kernel(const float* __restrict__ value,
                     const float* __restrict__ W_v,
                     const float* __restrict__ b_v)
{
    sgemm_body(value, W_v, b_v, g_img, B_ * HW_, D_, D_, D_);
}

// GEMM2: g_part[z] = weighted[:, z*512:(z+1)*512] @ W_out[z*512:(z+1)*512, :]
__global__ __launch_bounds__(256, 2)
void gemm_out_kernel(const float* __restrict__ W_out)
{
    sgemm_body(g_weighted, W_out, nullptr, g_part, BQ, D_, NH * D_, KLEN2);
}

// =====================================================================
// Offsets + attention logits + softmax + sampling locations
// 8 queries per block, 128 threads.
// =====================================================================
__global__ __launch_bounds__(128)
void locs_kernel(const float* __restrict__ query,
                 const float* __restrict__ refpts,
                 const float* __restrict__ W_off, const float* __restrict__ b_off,
                 const float* __restrict__ W_attn, const float* __restrict__ b_attn)
{
    __shared__ float qs[8][D_];
    __shared__ float res[8][96];

    const int t  = threadIdx.x;
    const int g0 = blockIdx.x * 8;   // base global query index (b*Q+q)

    // load 8 query rows (2048 floats) as float4
    const float4* src = (const float4*)(query + (size_t)g0 * D_);
    float4* dst = (float4*)&qs[0][0];
#pragma unroll
    for (int i = 0; i < 4; i++) dst[t + 128 * i] = src[t + 128 * i];
    __syncthreads();

    if (t < 96) {
        const float* Wcol;
        int stride;
        float bj;
        if (t < 64) { Wcol = W_off + t;         stride = NH * NP * 2; bj = b_off[t]; }
        else        { Wcol = W_attn + (t - 64); stride = NH * NP;     bj = b_attn[t - 64]; }
        float acc[8];
#pragma unroll
        for (int qi = 0; qi < 8; qi++) acc[qi] = bj;
        for (int k = 0; k < D_; k++) {
            float w = Wcol[(size_t)k * stride];
#pragma unroll
            for (int qi = 0; qi < 8; qi++) acc[qi] = fmaf(w, qs[qi][k], acc[qi]);
        }
#pragma unroll
        for (int qi = 0; qi < 8; qi++) res[qi][t] = acc[qi];
    }
    __syncthreads();

#pragma unroll
    for (int rep = 0; rep < 2; rep++) {
        int item = t + rep * 128;           // 0..255 : 8 queries x 32 (h,p)
        int qi = item >> 5;
        int hp = item & 31;
        int h  = hp >> 2;
        int p  = hp & 3;

        float l0 = res[qi][64 + h * 4 + 0];
        float l1 = res[qi][64 + h * 4 + 1];
        float l2 = res[qi][64 + h * 4 + 2];
        float l3 = res[qi][64 + h * 4 + 3];
        float m  = fmaxf(fmaxf(l0, l1), fmaxf(l2, l3));
        float e0 = expf(l0 - m), e1 = expf(l1 - m), e2 = expf(l2 - m), e3 = expf(l3 - m);
        float s  = e0 + e1 + e2 + e3;
        float ep = (p == 0) ? e0 : (p == 1) ? e1 : (p == 2) ? e2 : e3;

        int gq = g0 + qi;
        float ox = res[qi][h * 8 + p * 2 + 0];
        float oy = res[qi][h * 8 + p * 2 + 1];
        float rx = refpts[gq * 2 + 0];
        float ry = refpts[gq * 2 + 1];
        float lx = fminf(fmaxf(fmaf(ox, 0.1f, rx), 0.f), 1.f) * 2.f - 1.f;
        float ly = fminf(fmaxf(fmaf(oy, 0.1f, ry), 0.f), 1.f) * 2.f - 1.f;

        int idx = gq * (NH * NP) + hp;
        g_locs[idx * 2 + 0] = lx;
        g_locs[idx * 2 + 1] = ly;
        g_attn[idx]         = ep / s;
    }
}

// =====================================================================
// Bilinear sampling + attention-weighted reduce over points.
// One block per query (256 threads = 8 warps, warp = head).
// Lane owns channels lane*4..+3 and 128+lane*4..+3 (two float4).
// =====================================================================
__global__ __launch_bounds__(256)
void sample_kernel()
{
    const int gq   = blockIdx.x;          // 0..BQ-1
    const int b    = gq >> 10;            // Q_ = 1024
    const int h    = threadIdx.x >> 5;
    const int lane = threadIdx.x & 31;

    const float* imgb = g_img + (size_t)b * HW_ * D_;

    float4 acc0 = {0.f, 0.f, 0.f, 0.f};
    float4 acc1 = {0.f, 0.f, 0.f, 0.f};

#pragma unroll
    for (int p = 0; p < NP; p++) {
        int idx  = gq * (NH * NP) + h * NP + p;
        float lx = g_locs[idx * 2 + 0];
        float ly = g_locs[idx * 2 + 1];
        float aw = g_attn[idx];

        // align_corners=False mapping, H=W=128: x = 64*lx + 63.5
        float x = fmaf(lx, 64.f, 63.5f);
        float y = fmaf(ly, 64.f, 63.5f);
        float x0f = floorf(x), y0f = floorf(y);
        float fx = x - x0f, fy = y - y0f;
        int x0 = (int)x0f, y0 = (int)y0f;

        float w00 = (1.f - fx) * (1.f - fy) * aw;
        float w10 = fx * (1.f - fy) * aw;
        float w01 = (1.f - fx) * fy * aw;
        float w11 = fx * fy * aw;

        int xs[4] = {x0, x0 + 1, x0,     x0 + 1};
        int ys[4] = {y0, y0,     y0 + 1, y0 + 1};
        float ws[4] = {w00, w10, w01, w11};

#pragma unroll
        for (int c = 0; c < 4; c++) {
            int xi = xs[c], yi = ys[c];
            if (xi >= 0 && xi < Ww && yi >= 0 && yi < Hh) {   // uniform across warp
                float w = ws[c];
                const float4* row = (const float4*)(imgb + (size_t)(yi * Ww + xi) * D_);
                float4 v0 = row[lane];
                float4 v1 = row[lane + 32];
                acc0.x = fmaf(w, v0.x, acc0.x); acc0.y = fmaf(w, v0.y, acc0.y);
                acc0.z = fmaf(w, v0.z, acc0.z); acc0.w = fmaf(w, v0.w, acc0.w);
                acc1.x = fmaf(w, v1.x, acc1.x); acc1.y = fmaf(w, v1.y, acc1.y);
                acc1.z = fmaf(w, v1.z, acc1.z); acc1.w = fmaf(w, v1.w, acc1.w);
            }
        }
    }

    float* outp = g_weighted + ((size_t)gq * NH + h) * D_;
    ((float4*)outp)[lane]      = acc0;
    ((float4*)outp)[lane + 32] = acc1;
}

// =====================================================================
// Split-K reduction + bias -> final output (reads g_part by symbol)
// =====================================================================
__global__ __launch_bounds__(256)
void reduce_kernel(const float* __restrict__ bias, float* __restrict__ out)
{
    const int i = blockIdx.x * blockDim.x + threadIdx.x;  // float4 index
    const int stride4 = BQ * D_ / 4;                       // per-split size in float4
    float4 s = ((const float4*)bias)[i & (D_ / 4 - 1)];
    const float4* p = (const float4*)g_part;
#pragma unroll
    for (int z = 0; z < SPLITS; z++) {
        float4 v = p[(size_t)z * stride4 + i];
        s.x += v.x; s.y += v.y; s.z += v.z; s.w += v.w;
    }
    ((float4*)out)[i] = s;
}

// =====================================================================
// launch — kernel launches ONLY, no runtime API calls (capture-safe)
// =====================================================================
extern "C" void kernel_launch(void* const* d_in, const int* in_sizes, int n_in,
                              void* d_out, int out_size)
{
    const float* query  = (const float*)d_in[0];   // [B,Q,D]
    const float* refpts = (const float*)d_in[1];   // [B,Q,2]
    const float* value  = (const float*)d_in[2];   // [B,HW,D]
    const float* W_off  = (const float*)d_in[3];   // [D, 64]
    const float* b_off  = (const float*)d_in[4];   // [64]
    const float* W_attn = (const float*)d_in[5];   // [D, 32]
    const float* b_attn = (const float*)d_in[6];   // [32]
    const float* W_v    = (const float*)d_in[7];   // [D, D]
    const float* b_v    = (const float*)d_in[8];   // [D]
    const float* W_out  = (const float*)d_in[9];   // [NH*D, D]
    const float* b_out  = (const float*)d_in[10];  // [D]
    float* out = (float*)d_out;                    // [B,Q,D]

    // 1) img = value @ W_v + b_v      [65536,256] x [256,256]
    {
        dim3 grid((B_ * HW_) / TM, D_ / TN, 1);
        gemm_img_kernel<<<grid, 256>>>(value, W_v, b_v);
    }

    // 2) offsets / attention / sampling locations
    locs_kernel<<<BQ / 8, 128>>>(query, refpts, W_off, b_off, W_attn, b_attn);

    // 3) bilinear gather + weighted reduce over points
    sample_kernel<<<BQ, 256>>>();

    // 4) out = weighted @ W_out + b_out   [4096,2048] x [2048,256], split-K=4
    {
        dim3 grid(BQ / TM, D_ / TN, SPLITS);
        gemm_out_kernel<<<grid, 256>>>(W_out);
        reduce_kernel<<<(BQ * D_ / 4) / 256, 256>>>(b_out, out);
    }
}

// round 17
// speedup vs baseline: 1.7414x; 1.7414x over previous
#include <cuda_runtime.h>
#include <cstdint>

// Problem constants (fixed by the reference setup)
#define B_   4
#define Q_   1024
#define D_   256
#define Hh   128
#define Ww   128
#define HW_  (Hh * Ww)
#define NH   8
#define NP   4
#define BQ   (B_ * Q_)          // 4096
#define SPLITS 4                 // split-K for final GEMM
#define KLEN2  ((NH * D_) / SPLITS)      // 2048/4 = 512

// ---------------- scratch (device globals; no allocations) ----------------
// Referenced ONLY from device code (by symbol); kernel_launch does no runtime
// API calls, so graph capture bakes nothing host-computed.
__device__ float g_sampled[(size_t)BQ * NH * D_];     // 32 MB: [bq][h][d] raw-value samples
__device__ float g_part[(size_t)SPLITS * BQ * D_];    // 16 MB: split-K partials
__device__ float g_wcomb[(size_t)NH * D_ * D_];       //  2 MB: W_v @ W_out_h, stacked [2048,256]
__device__ float g_locs[(size_t)BQ * NH * NP * 2];    //  2 MB
__device__ float g_attn[(size_t)BQ * NH * NP];        //  0.5 MB
__device__ float g_s[(size_t)BQ * NH];                //  128 KB: padding-valid scalar per (bq,h)
__device__ float g_bvw[NH * D_];                      //  8 KB: b_v @ W_out_h

// =====================================================================
// SGEMM body: C[row0:+128, col0:+128] += A[:, k0:k0+kLen] * B rows
// Tile 128x128, TK=8, 256 threads, 8x8 microtile.
// Pointers are pre-offset by the wrapper (batch / split handled there).
// =====================================================================
#define TM 128
#define TN 128
#define TK 8

__device__ __forceinline__
void sgemm_body(const float* __restrict__ A, const float* __restrict__ Bm,
                float* __restrict__ C, int N, int K, int kLen, int k0)
{
    __shared__ float As[TK][TM];
    __shared__ float Bs[TK][TN];

    const int tid = threadIdx.x;
    const int tm  = tid >> 4;          // 0..15 -> rows tm*8..tm*8+7
    const int tn  = tid & 15;          // 0..15 -> cols tn*8..tn*8+7
    const int row0 = blockIdx.x * TM;
    const int col0 = blockIdx.y * TN;

    float acc[8][8];
#pragma unroll
    for (int i = 0; i < 8; i++)
#pragma unroll
        for (int j = 0; j < 8; j++) acc[i][j] = 0.f;

    // A tile loader: thread -> (row = tid/2, kk = (tid&1)*4), one float4
    const int arow = tid >> 1;
    const int akk  = (tid & 1) * 4;
    // B tile loader: thread -> (k = tid/32, col = (tid&31)*4), one float4
    const int bk   = tid >> 5;
    const int bcol = (tid & 31) * 4;

    const float* Aptr = A + (size_t)(row0 + arow) * K + k0 + akk;
    const float* Bptr = Bm + (size_t)(k0 + bk) * N + col0 + bcol;

    for (int kt = 0; kt < kLen; kt += TK) {
        float4 a4 = *(const float4*)Aptr;
        float4 b4 = *(const float4*)Bptr;
        __syncthreads();                 // previous compute done before smem overwrite
        As[akk + 0][arow] = a4.x;
        As[akk + 1][arow] = a4.y;
        As[akk + 2][arow] = a4.z;
        As[akk + 3][arow] = a4.w;
        *(float4*)&Bs[bk][bcol] = b4;
        __syncthreads();                 // tiles visible before compute

#pragma unroll
        for (int kk = 0; kk < TK; kk++) {
            float4 a0 = *(const float4*)&As[kk][tm * 8];
            float4 a1 = *(const float4*)&As[kk][tm * 8 + 4];
            float4 b0 = *(const float4*)&Bs[kk][tn * 8];
            float4 b1 = *(const float4*)&Bs[kk][tn * 8 + 4];
            float ar[8] = {a0.x, a0.y, a0.z, a0.w, a1.x, a1.y, a1.z, a1.w};
            float br[8] = {b0.x, b0.y, b0.z, b0.w, b1.x, b1.y, b1.z, b1.w};
#pragma unroll
            for (int i = 0; i < 8; i++)
#pragma unroll
                for (int j = 0; j < 8; j++)
                    acc[i][j] = fmaf(ar[i], br[j], acc[i][j]);
        }
        Aptr += TK;
        Bptr += (size_t)TK * N;
    }

    float* Cbase = C + (size_t)(row0 + tm * 8) * N + col0 + tn * 8;
#pragma unroll
    for (int i = 0; i < 8; i++) {
        float4 o0 = {acc[i][0], acc[i][1], acc[i][2], acc[i][3]};
        float4 o1 = {acc[i][4], acc[i][5], acc[i][6], acc[i][7]};
        *(float4*)(Cbase + (size_t)i * N)     = o0;
        *(float4*)(Cbase + (size_t)i * N + 4) = o1;
    }
}

// Wcomb precompute: for each head h, g_wcomb[h] = W_v @ W_out_h  ([256,256])
// grid (2, 2, 8)
__global__ __launch_bounds__(256, 2)
void gemm_wcomb_kernel(const float* __restrict__ W_v,
                       const float* __restrict__ W_out)
{
    const int h = blockIdx.z;
    sgemm_body(W_v,
               W_out   + (size_t)h * D_ * D_,
               g_wcomb + (size_t)h * D_ * D_,
               D_, D_, D_, 0);
}

// Final GEMM (split-K): g_part[z] = sampled[:, z*512:+512] @ Wcomb[z*512:+512, :]
// grid (32, 2, SPLITS)
__global__ __launch_bounds__(256, 2)
void gemm_out_kernel()
{
    const int z = blockIdx.z;
    sgemm_body(g_sampled, g_wcomb,
               g_part + (size_t)z * BQ * D_,
               D_, NH * D_, KLEN2, z * KLEN2);
}

// bvW[h] = b_v @ W_out_h   (8 blocks x 256 threads)
__global__ __launch_bounds__(256)
void bvw_kernel(const float* __restrict__ b_v, const float* __restrict__ W_out)
{
    const int h = blockIdx.x;
    const int n = threadIdx.x;
    float s = 0.f;
    const float* Wp = W_out + (size_t)h * D_ * D_ + n;
    for (int d = 0; d < D_; d++)
        s = fmaf(b_v[d], Wp[(size_t)d * D_], s);
    g_bvw[h * D_ + n] = s;
}

// =====================================================================
// Offsets + attention logits + softmax + sampling locations
// 8 queries per block, 128 threads.
// =====================================================================
__global__ __launch_bounds__(128)
void locs_kernel(const float* __restrict__ query,
                 const float* __restrict__ refpts,
                 const float* __restrict__ W_off, const float* __restrict__ b_off,
                 const float* __restrict__ W_attn, const float* __restrict__ b_attn)
{
    __shared__ float qs[8][D_];
    __shared__ float res[8][96];

    const int t  = threadIdx.x;
    const int g0 = blockIdx.x * 8;   // base global query index (b*Q+q)

    // load 8 query rows (2048 floats) as float4
    const float4* src = (const float4*)(query + (size_t)g0 * D_);
    float4* dst = (float4*)&qs[0][0];
#pragma unroll
    for (int i = 0; i < 4; i++) dst[t + 128 * i] = src[t + 128 * i];
    __syncthreads();

    if (t < 96) {
        const float* Wcol;
        int stride;
        float bj;
        if (t < 64) { Wcol = W_off + t;         stride = NH * NP * 2; bj = b_off[t]; }
        else        { Wcol = W_attn + (t - 64); stride = NH * NP;     bj = b_attn[t - 64]; }
        float acc[8];
#pragma unroll
        for (int qi = 0; qi < 8; qi++) acc[qi] = bj;
        for (int k = 0; k < D_; k++) {
            float w = Wcol[(size_t)k * stride];
#pragma unroll
            for (int qi = 0; qi < 8; qi++) acc[qi] = fmaf(w, qs[qi][k], acc[qi]);
        }
#pragma unroll
        for (int qi = 0; qi < 8; qi++) res[qi][t] = acc[qi];
    }
    __syncthreads();

#pragma unroll
    for (int rep = 0; rep < 2; rep++) {
        int item = t + rep * 128;           // 0..255 : 8 queries x 32 (h,p)
        int qi = item >> 5;
        int hp = item & 31;
        int h  = hp >> 2;
        int p  = hp & 3;

        float l0 = res[qi][64 + h * 4 + 0];
        float l1 = res[qi][64 + h * 4 + 1];
        float l2 = res[qi][64 + h * 4 + 2];
        float l3 = res[qi][64 + h * 4 + 3];
        float m  = fmaxf(fmaxf(l0, l1), fmaxf(l2, l3));
        float e0 = expf(l0 - m), e1 = expf(l1 - m), e2 = expf(l2 - m), e3 = expf(l3 - m);
        float s  = e0 + e1 + e2 + e3;
        float ep = (p == 0) ? e0 : (p == 1) ? e1 : (p == 2) ? e2 : e3;

        int gq = g0 + qi;
        float ox = res[qi][h * 8 + p * 2 + 0];
        float oy = res[qi][h * 8 + p * 2 + 1];
        float rx = refpts[gq * 2 + 0];
        float ry = refpts[gq * 2 + 1];
        float lx = fminf(fmaxf(fmaf(ox, 0.1f, rx), 0.f), 1.f) * 2.f - 1.f;
        float ly = fminf(fmaxf(fmaf(oy, 0.1f, ry), 0.f), 1.f) * 2.f - 1.f;

        int idx = gq * (NH * NP) + hp;
        g_locs[idx * 2 + 0] = lx;
        g_locs[idx * 2 + 1] = ly;
        g_attn[idx]         = ep / s;
    }
}

// =====================================================================
// Bilinear sampling of RAW value + attention-weighted reduce over points.
// One block per query (256 threads = 8 warps, warp = head).
// Lane owns channels lane*4..+3 and 128+lane*4..+3 (two float4).
// Also accumulates s = sum_p attn_p * (sum of valid corner weights),
// the coefficient of the b_v bias under zero-padding.
// =====================================================================
__global__ __launch_bounds__(256)
void sample_kernel(const float* __restrict__ value)
{
    const int gq   = blockIdx.x;          // 0..BQ-1
    const int b    = gq >> 10;            // Q_ = 1024
    const int h    = threadIdx.x >> 5;
    const int lane = threadIdx.x & 31;

    const float* valb = value + (size_t)b * HW_ * D_;

    float4 acc0 = {0.f, 0.f, 0.f, 0.f};
    float4 acc1 = {0.f, 0.f, 0.f, 0.f};
    float  ssum = 0.f;

#pragma unroll
    for (int p = 0; p < NP; p++) {
        int idx  = gq * (NH * NP) + h * NP + p;
        float lx = g_locs[idx * 2 + 0];
        float ly = g_locs[idx * 2 + 1];
        float aw = g_attn[idx];

        // align_corners=False mapping, H=W=128: x = 64*lx + 63.5
        float x = fmaf(lx, 64.f, 63.5f);
        float y = fmaf(ly, 64.f, 63.5f);
        float x0f = floorf(x), y0f = floorf(y);
        float fx = x - x0f, fy = y - y0f;
        int x0 = (int)x0f, y0 = (int)y0f;

        float w00 = (1.f - fx) * (1.f - fy) * aw;
        float w10 = fx * (1.f - fy) * aw;
        float w01 = (1.f - fx) * fy * aw;
        float w11 = fx * fy * aw;

        int xs[4] = {x0, x0 + 1, x0,     x0 + 1};
        int ys[4] = {y0, y0,     y0 + 1, y0 + 1};
        float ws[4] = {w00, w10, w01, w11};

#pragma unroll
        for (int c = 0; c < 4; c++) {
            int xi = xs[c], yi = ys[c];
            if (xi >= 0 && xi < Ww && yi >= 0 && yi < Hh) {   // uniform across warp
                float w = ws[c];
                ssum += w;
                const float4* row = (const float4*)(valb + (size_t)(yi * Ww + xi) * D_);
                float4 v0 = row[lane];
                float4 v1 = row[lane + 32];
                acc0.x = fmaf(w, v0.x, acc0.x); acc0.y = fmaf(w, v0.y, acc0.y);
                acc0.z = fmaf(w, v0.z, acc0.z); acc0.w = fmaf(w, v0.w, acc0.w);
                acc1.x = fmaf(w, v1.x, acc1.x); acc1.y = fmaf(w, v1.y, acc1.y);
                acc1.z = fmaf(w, v1.z, acc1.z); acc1.w = fmaf(w, v1.w, acc1.w);
            }
        }
    }

    float* outp = g_sampled + ((size_t)gq * NH + h) * D_;
    ((float4*)outp)[lane]      = acc0;
    ((float4*)outp)[lane + 32] = acc1;
    if (lane == 0) g_s[gq * NH + h] = ssum;
}

// =====================================================================
// Split-K reduction + b_out + sum_h s[bq,h] * bvW[h]  -> final output
// =====================================================================
__global__ __launch_bounds__(256)
void reduce_kernel(const float* __restrict__ bias, float* __restrict__ out)
{
    const int i = blockIdx.x * blockDim.x + threadIdx.x;  // float4 index
    const int bq = i >> 6;                                 // D_/4 = 64
    const int n4 = i & 63;
    const int stride4 = BQ * D_ / 4;                       // per-split size in float4

    float4 s = ((const float4*)bias)[n4];
    const float4* p = (const float4*)g_part;
#pragma unroll
    for (int z = 0; z < SPLITS; z++) {
        float4 v = p[(size_t)z * stride4 + i];
        s.x += v.x; s.y += v.y; s.z += v.z; s.w += v.w;
    }
    const float4* bvw = (const float4*)g_bvw;
#pragma unroll
    for (int h = 0; h < NH; h++) {
        float sv = g_s[bq * NH + h];
        float4 bwv = bvw[h * 64 + n4];
        s.x = fmaf(sv, bwv.x, s.x);
        s.y = fmaf(sv, bwv.y, s.y);
        s.z = fmaf(sv, bwv.z, s.z);
        s.w = fmaf(sv, bwv.w, s.w);
    }
    ((float4*)out)[i] = s;
}

// =====================================================================
// launch — kernel launches ONLY, no runtime API calls (capture-safe)
// =====================================================================
extern "C" void kernel_launch(void* const* d_in, const int* in_sizes, int n_in,
                              void* d_out, int out_size)
{
    const float* query  = (const float*)d_in[0];   // [B,Q,D]
    const float* refpts = (const float*)d_in[1];   // [B,Q,2]
    const float* value  = (const float*)d_in[2];   // [B,HW,D]
    const float* W_off  = (const float*)d_in[3];   // [D, 64]
    const float* b_off  = (const float*)d_in[4];   // [64]
    const float* W_attn = (const float*)d_in[5];   // [D, 32]
    const float* b_attn = (const float*)d_in[6];   // [32]
    const float* W_v    = (const float*)d_in[7];   // [D, D]
    const float* b_v    = (const float*)d_in[8];   // [D]
    const float* W_out  = (const float*)d_in[9];   // [NH*D, D]
    const float* b_out  = (const float*)d_in[10];  // [D]
    float* out = (float*)d_out;                    // [B,Q,D]

    // 1) combined weights: Wcomb[h] = W_v @ W_out_h ; bvW[h] = b_v @ W_out_h
    {
        dim3 grid(2, 2, NH);
        gemm_wcomb_kernel<<<grid, 256>>>(W_v, W_out);
        bvw_kernel<<<NH, 256>>>(b_v, W_out);
    }

    // 2) offsets / attention / sampling locations
    locs_kernel<<<BQ / 8, 128>>>(query, refpts, W_off, b_off, W_attn, b_attn);

    // 3) bilinear gather of RAW value + weighted reduce over points (+ s scalar)
    sample_kernel<<<BQ, 256>>>(value);

    // 4) out = sampled @ Wcomb + b_out + s·bvW   [4096,2048] x [2048,256], split-K=4
    {
        dim3 grid(BQ / TM, D_ / TN, SPLITS);
        gemm_out_kernel<<<grid, 256>>>();
        reduce_kernel<<<(BQ * D_ / 4) / 256, 256>>>(b_out, out);
    }
}